// round 13
// baseline (speedup 1.0000x reference)
#include <cuda_runtime.h>
#include <cuda_fp16.h>
#include <math.h>

#define N_NODES 100000
#define N_EDGES 3200000
#define F_IN    128
#define NB      1000
#define RS      16          // f32 row stride for p1 (64B)
#define E4      (N_EDGES / 4)   // 800000 int4-edge groups

// 32-byte rows for q1 and ag1 (16 halves; [0..9]=dims, ag1 half[10]=count)
struct alignas(32) Row32 { uint4 a; uint4 b; };

// ---- scratch (__device__ globals; no allocations allowed) ----
__device__ Row32    d_q1[N_NODES];
__device__ Row32    d_ag1h[N_NODES];
__device__ float    d_p1[N_NODES * RS];
__device__ float    d_p2s[N_NODES];
__device__ float    d_r2[N_NODES];
__device__ float    d_inv[N_NODES];
__device__ float    d_ag2s[N_NODES];
__device__ float    d_pool[NB];
__device__ float    d_cntB[NB];
__device__ unsigned d_ticket;

// ---- grid barrier (sense via generation counter; g_arrive==0 at entry/exit)
__device__ unsigned          g_arrive = 0;
__device__ volatile unsigned g_gen    = 0;

__device__ __forceinline__ void grid_sync() {
    __threadfence();
    __syncthreads();
    if (threadIdx.x == 0) {
        unsigned gen = g_gen;               // read BEFORE arriving
        if (atomicAdd(&g_arrive, 1u) == gridDim.x - 1u) {
            g_arrive = 0;
            __threadfence();
            g_gen = gen + 1u;
        } else {
            while (g_gen == gen) { }
        }
        __threadfence();
    }
    __syncthreads();
}

// ---------------------------------------------------------------------------
// zero layout (uint4-granular), executed by tail blocks of k_proj
// ---------------------------------------------------------------------------
#define Z_AG1  (N_NODES * 2)
#define Z_AG2  (N_NODES / 4)
#define Z_PB   (2 * NB / 4)
#define Z_TOT  (Z_AG1 + Z_AG2 + Z_PB)        // 225500

#define PROJ_B  ((N_NODES + 127) / 128)      // 782
#define ZB      ((Z_TOT + 127) / 128)        // 1762
#define FUSED_B (PROJ_B + ZB)

// ---------------------------------------------------------------------------
// launch 1 (fused): blocks [0,PROJ_B): p1 = x@W1a (f32), q1 = x@W1b (f16)
//                   blocks [PROJ_B,..): zero ag1h/ag2s/pool/cntB/ticket
// ---------------------------------------------------------------------------
__global__ void __launch_bounds__(128) k_proj(const float* __restrict__ x,
                                              const float* __restrict__ W1) {
    const int b = blockIdx.x;
    const int t = threadIdx.x;

    if (b >= PROJ_B) {                       // ---- zeroing path ----
        int i = (b - PROJ_B) * 128 + t;
        uint4 z = make_uint4(0u, 0u, 0u, 0u);
        if (i < Z_AG1) ((uint4*)d_ag1h)[i] = z;
        else if (i < Z_AG1 + Z_AG2) ((uint4*)d_ag2s)[i - Z_AG1] = z;
        else if (i < Z_AG1 + Z_AG2 + Z_PB / 2) ((uint4*)d_pool)[i - Z_AG1 - Z_AG2] = z;
        else if (i < Z_TOT) ((uint4*)d_cntB)[i - Z_AG1 - Z_AG2 - Z_PB / 2] = z;
        if (i == 0) d_ticket = 0u;
        return;
    }

    __shared__ float Ws[F_IN * 20];     // Ws[f*20+o]: o<10 -> W1a, o>=10 -> W1b
    __shared__ float xs[128 * 33];

    for (int i = t; i < F_IN * 20; i += 128) {
        int f = i / 20, o = i % 20;
        Ws[i] = (o < 10) ? W1[f * 10 + o] : W1[(F_IN + f) * 10 + (o - 10)];
    }

    const int nodeBase = b * 128;
    float acc[20];
#pragma unroll
    for (int o = 0; o < 20; o++) acc[o] = 0.0f;

    for (int c = 0; c < 4; c++) {
        __syncthreads();
#pragma unroll
        for (int k = 0; k < 8; k++) {
            int idx = t + k * 128;
            int row = idx >> 3;
            int c4  = idx & 7;
            float4 v = make_float4(0.f, 0.f, 0.f, 0.f);
            int node = nodeBase + row;
            if (node < N_NODES)
                v = *(const float4*)(x + (size_t)node * F_IN + c * 32 + c4 * 4);
            float* xr = &xs[row * 33 + c4 * 4];
            xr[0] = v.x; xr[1] = v.y; xr[2] = v.z; xr[3] = v.w;
        }
        __syncthreads();
#pragma unroll
        for (int f = 0; f < 32; f++) {
            float xv = xs[t * 33 + f];
            const float* wr = &Ws[(c * 32 + f) * 20];
            float4 w0 = *(const float4*)(wr + 0);
            float4 w1 = *(const float4*)(wr + 4);
            float4 w2 = *(const float4*)(wr + 8);
            float4 w3 = *(const float4*)(wr + 12);
            float4 w4 = *(const float4*)(wr + 16);
            acc[0]  += xv * w0.x; acc[1]  += xv * w0.y; acc[2]  += xv * w0.z; acc[3]  += xv * w0.w;
            acc[4]  += xv * w1.x; acc[5]  += xv * w1.y; acc[6]  += xv * w1.z; acc[7]  += xv * w1.w;
            acc[8]  += xv * w2.x; acc[9]  += xv * w2.y; acc[10] += xv * w2.z; acc[11] += xv * w2.w;
            acc[12] += xv * w3.x; acc[13] += xv * w3.y; acc[14] += xv * w3.z; acc[15] += xv * w3.w;
            acc[16] += xv * w4.x; acc[17] += xv * w4.y; acc[18] += xv * w4.z; acc[19] += xv * w4.w;
        }
    }

    const int node = nodeBase + t;
    if (node < N_NODES) {
        float* pr = d_p1 + (size_t)node * RS;
        *(float4*)(pr + 0) = make_float4(acc[0], acc[1], acc[2], acc[3]);
        *(float4*)(pr + 4) = make_float4(acc[4], acc[5], acc[6], acc[7]);
        *(float2*)(pr + 8) = make_float2(acc[8], acc[9]);
        __half2 h[5];
#pragma unroll
        for (int i = 0; i < 5; i++)
            h[i] = __floats2half2_rn(acc[10 + 2 * i], acc[11 + 2 * i]);
        Row32* qr = &d_q1[node];
        qr->a = make_uint4(*(unsigned*)&h[0], *(unsigned*)&h[1],
                           *(unsigned*)&h[2], *(unsigned*)&h[3]);
        qr->b = make_uint4(*(unsigned*)&h[4], 0u, 0u, 0u);
    }
}

// ---------------------------------------------------------------------------
// launch 2 (cooperative): edge1 -> grid barrier -> layer2s
// ---------------------------------------------------------------------------
__global__ void __launch_bounds__(256)
k_B(const int* __restrict__ src, const int* __restrict__ dst,
    const float* __restrict__ W2, const float* __restrict__ Wfc) {
    const int t    = threadIdx.x;
    const int gsz  = gridDim.x * 256;
    const int gtid = blockIdx.x * 256 + t;

    __shared__ float uv[20];    // [0..9]=u=W2a@Wfc, [10..19]=v=W2b@Wfc
    if (t < 20) {
        int j = t % 10;
        int base = (t < 10) ? j * 10 : (10 + j) * 10;
        float s = 0.0f;
#pragma unroll
        for (int o = 0; o < 10; o++) s += W2[base + o] * Wfc[o];
        uv[t] = s;
    }

    // ---- phase 1: edge1.  ag1h[dst] += {q1[src], 1.0h} ----
    for (int i = gtid; i < E4; i += gsz) {
        int4 s4 = ((const int4*)src)[i];
        int4 d4 = ((const int4*)dst)[i];
        int ss[4] = {s4.x, s4.y, s4.z, s4.w};
        int dd[4] = {d4.x, d4.y, d4.z, d4.w};
        uint4 ua[4]; unsigned u4[4];
#pragma unroll
        for (int k = 0; k < 4; k++) {
            const Row32* qp = &d_q1[ss[k]];
            ua[k] = qp->a;
            u4[k] = qp->b.x;
        }
#pragma unroll
        for (int k = 0; k < 4; k++) {
            Row32* dr = &d_ag1h[dd[k]];
            asm volatile("red.global.add.noftz.v4.f16x2 [%0], {%1,%2,%3,%4};"
                         :: "l"(dr), "r"(ua[k].x), "r"(ua[k].y), "r"(ua[k].z), "r"(ua[k].w)
                         : "memory");
            asm volatile("red.global.add.noftz.v2.f16x2 [%0], {%1,%2};"
                         :: "l"((char*)dr + 16), "r"(u4[k]), "r"(0x00003C00u) : "memory");
        }
    }
    grid_sync();                // ag1h complete; also makes uv visible

    // ---- phase 2: layer2s ----
    for (int node = gtid; node < N_NODES; node += gsz) {
        uint4 au = d_ag1h[node].a;
        uint4 bu = d_ag1h[node].b;
        float2 f0 = __half22float2(*(__half2*)&au.x);
        float2 f1 = __half22float2(*(__half2*)&au.y);
        float2 f2 = __half22float2(*(__half2*)&au.z);
        float2 f3 = __half22float2(*(__half2*)&au.w);
        float2 f4 = __half22float2(*(__half2*)&bu.x);
        float  cntf = __half2float(__low2half(*(__half2*)&bu.y));
        float inv = 1.0f / fmaxf(cntf, 1.0f);

        const float* p = d_p1 + (size_t)node * RS;
        float4 p0 = *(const float4*)(p + 0), p1v = *(const float4*)(p + 4);
        float2 p2v = *(const float2*)(p + 8);

        float h[10];
        h[0] = fmaxf(p0.x + f0.x * inv, 0.f); h[1] = fmaxf(p0.y + f0.y * inv, 0.f);
        h[2] = fmaxf(p0.z + f1.x * inv, 0.f); h[3] = fmaxf(p0.w + f1.y * inv, 0.f);
        h[4] = fmaxf(p1v.x + f2.x * inv, 0.f); h[5] = fmaxf(p1v.y + f2.y * inv, 0.f);
        h[6] = fmaxf(p1v.z + f3.x * inv, 0.f); h[7] = fmaxf(p1v.w + f3.y * inv, 0.f);
        h[8] = fmaxf(p2v.x + f4.x * inv, 0.f); h[9] = fmaxf(p2v.y + f4.y * inv, 0.f);

        float ps = 0.0f, rs = 0.0f;
#pragma unroll
        for (int j = 0; j < 10; j++) {
            ps += h[j] * uv[j];
            rs += h[j] * uv[10 + j];
        }
        d_p2s[node] = ps;
        d_r2[node]  = rs;
        d_inv[node] = inv;
    }
}

// ---------------------------------------------------------------------------
// launch 3 (cooperative): edge2 -> grid barrier -> pool -> ticketed out
// ---------------------------------------------------------------------------
__global__ void __launch_bounds__(256)
k_C(const int* __restrict__ src, const int* __restrict__ dst,
    const int* __restrict__ batch, float* __restrict__ out) {
    const int t    = threadIdx.x;
    const int gsz  = gridDim.x * 256;
    const int gtid = blockIdx.x * 256 + t;

    // ---- phase 1: edge2.  ag2s[dst] += r2[src] ----
    for (int i = gtid; i < E4; i += gsz) {
        int4 s4 = ((const int4*)src)[i];
        int4 d4 = ((const int4*)dst)[i];
        float v0 = __ldg(&d_r2[s4.x]);
        float v1 = __ldg(&d_r2[s4.y]);
        float v2 = __ldg(&d_r2[s4.z]);
        float v3 = __ldg(&d_r2[s4.w]);
        atomicAdd(&d_ag2s[d4.x], v0);
        atomicAdd(&d_ag2s[d4.y], v1);
        atomicAdd(&d_ag2s[d4.z], v2);
        atomicAdd(&d_ag2s[d4.w], v3);
    }
    grid_sync();                // ag2s complete

    // ---- phase 2: pool (warp-aggregated; batch sorted, node blocks of 32) ----
    for (int node = gtid; node < N_NODES; node += gsz) {
        float s = d_p2s[node] + d_ag2s[node] * d_inv[node];
        int b = batch[node];
        int b_last  = __shfl_sync(0xffffffffu, b, 31);
        int b_first = __shfl_sync(0xffffffffu, b, 0);
        if (b_first == b_last) {
            float ssum = s;
#pragma unroll
            for (int d = 16; d > 0; d >>= 1)
                ssum += __shfl_xor_sync(0xffffffffu, ssum, d);
            if ((t & 31) == 0) {
                atomicAdd(&d_pool[b], ssum);
                atomicAdd(&d_cntB[b], 32.0f);
            }
        } else {
            atomicAdd(&d_pool[b], s);
            atomicAdd(&d_cntB[b], 1.0f);
        }
    }

    // ---- phase 3: last finishing block writes out ----
    __threadfence();
    __syncthreads();
    __shared__ bool last;
    if (t == 0) {
        unsigned tk = atomicAdd(&d_ticket, 1u);
        last = (tk == gridDim.x - 1);
    }
    __syncthreads();
    if (last) {
        __threadfence();
        for (int bb = t; bb < NB; bb += 256) {
            float g = d_pool[bb] / fmaxf(d_cntB[bb], 1.0f);
            out[bb] = 1.0f / (1.0f + expf(-g));
        }
    }
}

// ---------------------------------------------------------------------------
static void launch_coop_B(const int* src, const int* dst,
                          const float* W2, const float* Wfc, int sms) {
    int occ = 1;
    cudaOccupancyMaxActiveBlocksPerMultiprocessor(&occ, k_B, 256, 0);
    if (occ < 1) occ = 1;
    cudaLaunchConfig_t cfg = {};
    cfg.gridDim  = dim3((unsigned)(sms * occ), 1, 1);
    cfg.blockDim = dim3(256, 1, 1);
    cudaLaunchAttribute a[1];
    a[0].id = cudaLaunchAttributeCooperative;
    a[0].val.cooperative = 1;
    cfg.attrs = a; cfg.numAttrs = 1;
    cudaLaunchKernelEx(&cfg, k_B, src, dst, W2, Wfc);
}

static void launch_coop_C(const int* src, const int* dst,
                          const int* batch, float* out, int sms) {
    int occ = 1;
    cudaOccupancyMaxActiveBlocksPerMultiprocessor(&occ, k_C, 256, 0);
    if (occ < 1) occ = 1;
    cudaLaunchConfig_t cfg = {};
    cfg.gridDim  = dim3((unsigned)(sms * occ), 1, 1);
    cfg.blockDim = dim3(256, 1, 1);
    cudaLaunchAttribute a[1];
    a[0].id = cudaLaunchAttributeCooperative;
    a[0].val.cooperative = 1;
    cfg.attrs = a; cfg.numAttrs = 1;
    cudaLaunchKernelEx(&cfg, k_C, src, dst, batch, out);
}

extern "C" void kernel_launch(void* const* d_in, const int* in_sizes, int n_in,
                              void* d_out, int out_size) {
    const float* x   = (const float*)d_in[0];
    const int*   ei  = (const int*)d_in[1];
    const int*   bat = (const int*)d_in[2];
    const float* W1  = (const float*)d_in[3];
    const float* W2  = (const float*)d_in[4];
    const float* Wfc = (const float*)d_in[5];
    float* out = (float*)d_out;

    const int* src = ei;
    const int* dst = ei + N_EDGES;

    int dev = 0, sms = 148;
    cudaGetDevice(&dev);
    cudaDeviceGetAttribute(&sms, cudaDevAttrMultiProcessorCount, dev);

    k_proj<<<FUSED_B, 128>>>(x, W1);            // 1
    launch_coop_B(src, dst, W2, Wfc, sms);      // 2
    launch_coop_C(src, dst, bat, out, sms);     // 3
}

// round 14
// speedup vs baseline: 1.3157x; 1.3157x over previous
#include <cuda_runtime.h>
#include <cuda_fp16.h>
#include <math.h>

#define N_NODES 100000
#define N_EDGES 3200000
#define F_IN    128
#define NB      1000
#define RS      16          // f32 row stride for p1 (64B)
#define E4      (N_EDGES / 4)

// 32-byte rows for q1 and ag1 (16 halves; [0..9]=dims, ag1 half[10]=count)
struct alignas(32) Row32 { uint4 a; uint4 b; };

// ---- scratch (__device__ globals; no allocations allowed) ----
__device__ Row32    d_q1[N_NODES];
__device__ Row32    d_ag1h[N_NODES];
__device__ float    d_p1[N_NODES * RS];
__device__ float    d_p2s[N_NODES];
__device__ float    d_r2[N_NODES];
__device__ float    d_inv[N_NODES];
__device__ float    d_ag2s[N_NODES];
__device__ float    d_pool[NB];
__device__ float    d_cntB[NB];
__device__ unsigned d_ticket;

// ---------------------------------------------------------------------------
// zero layout (uint4-granular), executed by tail blocks of k_proj
// ---------------------------------------------------------------------------
#define Z_AG1  (N_NODES * 2)
#define Z_AG2  (N_NODES / 4)
#define Z_PB   (2 * NB / 4)
#define Z_TOT  (Z_AG1 + Z_AG2 + Z_PB)        // 225500

#define PROJ_B  ((N_NODES + 127) / 128)      // 782 (128 nodes/block, 8 warps x 16)
#define ZB      ((Z_TOT + 255) / 256)        // 881
#define FUSED_B (PROJ_B + ZB)

__device__ __forceinline__ unsigned smem_u32(const void* p) {
    return (unsigned)__cvta_generic_to_shared(p);
}

// ---------------------------------------------------------------------------
// launch 1 (fused): blocks [0,PROJ_B): tensor-core proj (p1 f32, q1 f16)
//                   blocks [PROJ_B,..): zero ag1h/ag2s/pool/cntB/ticket
// C[100000x20] = X[100000x128] @ W[128x20]  via mma.m16n8k16 f16 (f32 accum)
// ---------------------------------------------------------------------------
__global__ void __launch_bounds__(256) k_proj(const float* __restrict__ x,
                                              const float* __restrict__ W1) {
    const int b = blockIdx.x;
    const int t = threadIdx.x;

    if (b >= PROJ_B) {                       // ---- zeroing path ----
        int i = (b - PROJ_B) * 256 + t;
        uint4 z = make_uint4(0u, 0u, 0u, 0u);
        if (i < Z_AG1) ((uint4*)d_ag1h)[i] = z;
        else if (i < Z_AG1 + Z_AG2) ((uint4*)d_ag2s)[i - Z_AG1] = z;
        else if (i < Z_AG1 + Z_AG2 + Z_PB / 2) ((uint4*)d_pool)[i - Z_AG1 - Z_AG2] = z;
        else if (i < Z_TOT) ((uint4*)d_cntB)[i - Z_AG1 - Z_AG2 - Z_PB / 2] = z;
        if (i == 0) d_ticket = 0u;
        return;
    }

    __shared__ __half Wh[128 * 24];              // W padded to 24 cols (6KB)
    __shared__ __half xs[8][16 * 136];           // per-warp 16x128 tile, 136-pad

    // stage Wh: cols 0..9 = W1a, 10..19 = W1b, 20..23 = 0
    for (int i = t; i < 128 * 24; i += 256) {
        int k = i / 24, n = i % 24;
        float v = (n < 10) ? W1[k * 10 + n]
                : (n < 20) ? W1[(F_IN + k) * 10 + (n - 10)] : 0.0f;
        Wh[i] = __float2half(v);
    }
    __syncthreads();

    const int wid  = t >> 5;
    const int lane = t & 31;
    const int gid  = lane >> 2;     // 0..7
    const int tig  = lane & 3;      // 0..3
    const int tb   = b * 128 + wid * 16;
    if (tb >= N_NODES) return;      // tail warps (after the only block sync)

    // ---- B fragments hoisted to registers: 8 ksteps x 3 ntiles x 2 regs ----
    unsigned bf[8][3][2];
#pragma unroll
    for (int ks = 0; ks < 8; ks++) {
#pragma unroll
        for (int nb = 0; nb < 3; nb++) {
            int col = nb * 8 + gid;
            int k0  = ks * 16 + tig * 2;
            __half2 lo = __halves2half2(Wh[k0 * 24 + col],       Wh[(k0 + 1) * 24 + col]);
            __half2 hi = __halves2half2(Wh[(k0 + 8) * 24 + col], Wh[(k0 + 9) * 24 + col]);
            bf[ks][nb][0] = *(unsigned*)&lo;
            bf[ks][nb][1] = *(unsigned*)&hi;
        }
    }

    // ---- stage this warp's 16x128 x-tile as f16 (coalesced 512B/row) ----
    __half* xw = xs[wid];
#pragma unroll
    for (int row = 0; row < 16; row++) {
        float4 v = *(const float4*)(x + (size_t)(tb + row) * F_IN + lane * 4);
        __half2 h0 = __floats2half2_rn(v.x, v.y);
        __half2 h1 = __floats2half2_rn(v.z, v.w);
        uint2 u = make_uint2(*(unsigned*)&h0, *(unsigned*)&h1);
        *(uint2*)(xw + row * 136 + lane * 4) = u;
    }
    __syncwarp();

    // ---- mainloop: 8 ksteps, ldmatrix.x4 A + 3 MMAs ----
    float c0[4] = {0, 0, 0, 0}, c1[4] = {0, 0, 0, 0}, c2[4] = {0, 0, 0, 0};
    unsigned abase = smem_u32(xw) + (lane & 15) * 272 + (lane >> 4) * 16;
#pragma unroll
    for (int ks = 0; ks < 8; ks++) {
        unsigned a0, a1, a2, a3;
        asm volatile("ldmatrix.sync.aligned.m8n8.x4.shared.b16 {%0,%1,%2,%3}, [%4];"
                     : "=r"(a0), "=r"(a1), "=r"(a2), "=r"(a3)
                     : "r"(abase + ks * 32));
        asm volatile("mma.sync.aligned.m16n8k16.row.col.f32.f16.f16.f32 "
                     "{%0,%1,%2,%3}, {%4,%5,%6,%7}, {%8,%9}, {%0,%1,%2,%3};"
                     : "+f"(c0[0]), "+f"(c0[1]), "+f"(c0[2]), "+f"(c0[3])
                     : "r"(a0), "r"(a1), "r"(a2), "r"(a3),
                       "r"(bf[ks][0][0]), "r"(bf[ks][0][1]));
        asm volatile("mma.sync.aligned.m16n8k16.row.col.f32.f16.f16.f32 "
                     "{%0,%1,%2,%3}, {%4,%5,%6,%7}, {%8,%9}, {%0,%1,%2,%3};"
                     : "+f"(c1[0]), "+f"(c1[1]), "+f"(c1[2]), "+f"(c1[3])
                     : "r"(a0), "r"(a1), "r"(a2), "r"(a3),
                       "r"(bf[ks][1][0]), "r"(bf[ks][1][1]));
        asm volatile("mma.sync.aligned.m16n8k16.row.col.f32.f16.f16.f32 "
                     "{%0,%1,%2,%3}, {%4,%5,%6,%7}, {%8,%9}, {%0,%1,%2,%3};"
                     : "+f"(c2[0]), "+f"(c2[1]), "+f"(c2[2]), "+f"(c2[3])
                     : "r"(a0), "r"(a1), "r"(a2), "r"(a3),
                       "r"(bf[ks][2][0]), "r"(bf[ks][2][1]));
    }

    // ---- epilogue: scatter C frags to p1 (f32) / q1 (f16) ----
    // thread covers rows {gid, gid+8}, cols {nb*8+2tig, +1}
    const float* cs[3] = {c0, c1, c2};
#pragma unroll
    for (int nb = 0; nb < 3; nb++) {
        int cbase = nb * 8 + tig * 2;
#pragma unroll
        for (int r = 0; r < 2; r++) {
            int n = tb + gid + r * 8;
            float lo = cs[nb][r * 2 + 0];
            float hi = cs[nb][r * 2 + 1];
            if (cbase <= 8) {                        // cols 0..9 -> p1
                *(float2*)&d_p1[(size_t)n * RS + cbase] = make_float2(lo, hi);
            } else if (cbase <= 18) {                // cols 10..19 -> q1 f16
                __half2 hh = __floats2half2_rn(lo, hi);
                ((unsigned*)&d_q1[n])[(cbase - 10) >> 1] = *(unsigned*)&hh;
            }                                        // cols 20..23 discarded
        }
    }
}

// ---------------------------------------------------------------------------
// launch 2: edge pass 1.  ag1h[dst] += {q1[src], 1.0h}   (4 edges/thread)
// ---------------------------------------------------------------------------
__global__ void __launch_bounds__(256) k_edge1(const int* __restrict__ src,
                                               const int* __restrict__ dst) {
    int i = blockIdx.x * blockDim.x + threadIdx.x;
    if (i >= E4) return;
    int4 s4 = ((const int4*)src)[i];
    int4 d4 = ((const int4*)dst)[i];
    int ss[4] = {s4.x, s4.y, s4.z, s4.w};
    int dd[4] = {d4.x, d4.y, d4.z, d4.w};
    uint4 ua[4]; unsigned u4[4];
#pragma unroll
    for (int k = 0; k < 4; k++) {
        const Row32* qp = &d_q1[ss[k]];
        ua[k] = qp->a;
        u4[k] = qp->b.x;
    }
#pragma unroll
    for (int k = 0; k < 4; k++) {
        Row32* dr = &d_ag1h[dd[k]];
        asm volatile("red.global.add.noftz.v4.f16x2 [%0], {%1,%2,%3,%4};"
                     :: "l"(dr), "r"(ua[k].x), "r"(ua[k].y), "r"(ua[k].z), "r"(ua[k].w)
                     : "memory");
        asm volatile("red.global.add.noftz.v2.f16x2 [%0], {%1,%2};"
                     :: "l"((char*)dr + 16), "r"(u4[k]), "r"(0x00003C00u) : "memory");
    }
}

// ---------------------------------------------------------------------------
// launch 3: h = relu(p1 + ag1/max(cnt,1));  p2s=h.u, r2=h.v, inv
// ---------------------------------------------------------------------------
__global__ void __launch_bounds__(256) k_layer2s(const float* __restrict__ W2,
                                                 const float* __restrict__ Wfc) {
    __shared__ float uv[20];    // [0..9]=u=W2a@Wfc, [10..19]=v=W2b@Wfc
    int t = threadIdx.x;
    if (t < 20) {
        int j = t % 10;
        int base = (t < 10) ? j * 10 : (10 + j) * 10;
        float s = 0.0f;
#pragma unroll
        for (int o = 0; o < 10; o++) s += W2[base + o] * Wfc[o];
        uv[t] = s;
    }
    __syncthreads();

    int node = blockIdx.x * blockDim.x + t;
    if (node >= N_NODES) return;

    uint4 au = d_ag1h[node].a;
    uint4 bu = d_ag1h[node].b;
    float2 f0 = __half22float2(*(__half2*)&au.x);
    float2 f1 = __half22float2(*(__half2*)&au.y);
    float2 f2 = __half22float2(*(__half2*)&au.z);
    float2 f3 = __half22float2(*(__half2*)&au.w);
    float2 f4 = __half22float2(*(__half2*)&bu.x);
    float  cntf = __half2float(__low2half(*(__half2*)&bu.y));
    float inv = 1.0f / fmaxf(cntf, 1.0f);

    const float* p = d_p1 + (size_t)node * RS;
    float4 p0 = *(const float4*)(p + 0), p1v = *(const float4*)(p + 4);
    float2 p2v = *(const float2*)(p + 8);

    float h[10];
    h[0] = fmaxf(p0.x + f0.x * inv, 0.f); h[1] = fmaxf(p0.y + f0.y * inv, 0.f);
    h[2] = fmaxf(p0.z + f1.x * inv, 0.f); h[3] = fmaxf(p0.w + f1.y * inv, 0.f);
    h[4] = fmaxf(p1v.x + f2.x * inv, 0.f); h[5] = fmaxf(p1v.y + f2.y * inv, 0.f);
    h[6] = fmaxf(p1v.z + f3.x * inv, 0.f); h[7] = fmaxf(p1v.w + f3.y * inv, 0.f);
    h[8] = fmaxf(p2v.x + f4.x * inv, 0.f); h[9] = fmaxf(p2v.y + f4.y * inv, 0.f);

    float ps = 0.0f, rs = 0.0f;
#pragma unroll
    for (int j = 0; j < 10; j++) {
        ps += h[j] * uv[j];
        rs += h[j] * uv[10 + j];
    }
    d_p2s[node] = ps;
    d_r2[node]  = rs;
    d_inv[node] = inv;
}

// ---------------------------------------------------------------------------
// launch 4 (profiled): edge pass 2 (scalar).  ag2s[dst] += r2[src]
// ---------------------------------------------------------------------------
__global__ void __launch_bounds__(256) k_edge2(const int* __restrict__ src,
                                               const int* __restrict__ dst) {
    int i = blockIdx.x * blockDim.x + threadIdx.x;
    if (i >= E4) return;
    int4 s4 = ((const int4*)src)[i];
    int4 d4 = ((const int4*)dst)[i];
    float v0 = __ldg(&d_r2[s4.x]);
    float v1 = __ldg(&d_r2[s4.y]);
    float v2 = __ldg(&d_r2[s4.z]);
    float v3 = __ldg(&d_r2[s4.w]);
    atomicAdd(&d_ag2s[d4.x], v0);
    atomicAdd(&d_ag2s[d4.y], v1);
    atomicAdd(&d_ag2s[d4.z], v2);
    atomicAdd(&d_ag2s[d4.w], v3);
}

// ---------------------------------------------------------------------------
// launch 5: pool (warp-aggregated; batch is sorted) + out (last block)
// ---------------------------------------------------------------------------
__global__ void __launch_bounds__(256) k_pool(const int* __restrict__ batch,
                                              float* __restrict__ out) {
    int node = blockIdx.x * blockDim.x + threadIdx.x;
    if (node < N_NODES) {
        float s = d_p2s[node] + d_ag2s[node] * d_inv[node];
        int b = batch[node];
        int b_last  = __shfl_sync(0xffffffffu, b, 31);
        int b_first = __shfl_sync(0xffffffffu, b, 0);
        if (b_first == b_last) {
            float ssum = s;
#pragma unroll
            for (int d = 16; d > 0; d >>= 1)
                ssum += __shfl_xor_sync(0xffffffffu, ssum, d);
            if ((threadIdx.x & 31) == 0) {
                atomicAdd(&d_pool[b], ssum);
                atomicAdd(&d_cntB[b], 32.0f);
            }
        } else {
            atomicAdd(&d_pool[b], s);
            atomicAdd(&d_cntB[b], 1.0f);
        }
    }
    __threadfence();
    __syncthreads();
    __shared__ bool last;
    if (threadIdx.x == 0) {
        unsigned tk = atomicAdd(&d_ticket, 1u);
        last = (tk == gridDim.x - 1);
    }
    __syncthreads();
    if (last) {
        __threadfence();
        for (int bb = threadIdx.x; bb < NB; bb += blockDim.x) {
            float g = d_pool[bb] / fmaxf(d_cntB[bb], 1.0f);
            out[bb] = 1.0f / (1.0f + expf(-g));
        }
    }
}

// ---------------------------------------------------------------------------
extern "C" void kernel_launch(void* const* d_in, const int* in_sizes, int n_in,
                              void* d_out, int out_size) {
    const float* x   = (const float*)d_in[0];
    const int*   ei  = (const int*)d_in[1];
    const int*   bat = (const int*)d_in[2];
    const float* W1  = (const float*)d_in[3];
    const float* W2  = (const float*)d_in[4];
    const float* Wfc = (const float*)d_in[5];
    float* out = (float*)d_out;

    const int* src = ei;
    const int* dst = ei + N_EDGES;

    k_proj<<<FUSED_B, 256>>>(x, W1);                                // 1
    k_edge1<<<(E4 + 255) / 256, 256>>>(src, dst);                   // 2
    k_layer2s<<<(N_NODES + 255) / 256, 256>>>(W2, Wfc);             // 3
    k_edge2<<<(E4 + 255) / 256, 256>>>(src, dst);                   // 4 (profiled)
    k_pool<<<(N_NODES + 255) / 256, 256>>>(bat, out);               // 5
}